// round 12
// baseline (speedup 1.0000x reference)
#include <cuda_runtime.h>
#include <cuda_bf16.h>
#include <cstdint>

// Shapes (fixed): B=4, LK=256, NQ=64, H=8, DK=DV=64, DM=512
#define B_ 4
#define LK_ 256
#define NQ_ 64
#define H_ 8
#define DM_ 512

// ---------------- scratch (device globals; no allocation) ----------------
__device__ float g_PQ[B_ * LK_ * DM_];
__device__ float g_PK[B_ * LK_ * DM_];
__device__ float g_PV[B_ * LK_ * DM_];
__device__ float g_PU[B_ * NQ_ * DM_];
__device__ float g_OUT[B_ * LK_ * DM_];
__device__ float g_A[B_ * LK_ * DM_];
__device__ float g_QT[B_ * LK_ * NQ_ * H_];
__device__ float g_VF[H_ * B_ * LK_ * DM_];
__device__ float g_MU[B_ * LK_ * NQ_];
__device__ float g_RS[B_ * LK_ * NQ_];

// ---------------- tf32 + f32x2 helpers ----------------
__device__ __forceinline__ uint32_t f2tf(float x) {
    uint32_t r;
    asm("cvt.rna.tf32.f32 %0, %1;" : "=r"(r) : "f"(x));
    return r;
}

__device__ __forceinline__ void mma_tf32(
    float& c0, float& c1, float& c2, float& c3,
    uint32_t a0, uint32_t a1, uint32_t a2, uint32_t a3,
    uint32_t b0, uint32_t b1)
{
    asm volatile(
        "mma.sync.aligned.m16n8k8.row.col.f32.tf32.tf32.f32 "
        "{%0,%1,%2,%3},{%4,%5,%6,%7},{%8,%9},{%0,%1,%2,%3};"
        : "+f"(c0), "+f"(c1), "+f"(c2), "+f"(c3)
        : "r"(a0), "r"(a1), "r"(a2), "r"(a3), "r"(b0), "r"(b1));
}

typedef unsigned long long u64t;

__device__ __forceinline__ u64t pk2(float lo, float hi) {
    u64t r;
    asm("mov.b64 %0, {%1, %2};" : "=l"(r) : "f"(lo), "f"(hi));
    return r;
}
__device__ __forceinline__ void upk2(u64t v, float& lo, float& hi) {
    asm("mov.b64 {%0, %1}, %2;" : "=f"(lo), "=f"(hi) : "l"(v));
}
__device__ __forceinline__ u64t fma2(u64t a, u64t b, u64t c) {
    u64t d;
    asm("fma.rn.f32x2 %0, %1, %2, %3;" : "=l"(d) : "l"(a), "l"(b), "l"(c));
    return d;
}
__device__ __forceinline__ u64t mul2(u64t a, u64t b) {
    u64t d;
    asm("mul.rn.f32x2 %0, %1, %2;" : "=l"(d) : "l"(a), "l"(b));
    return d;
}
__device__ __forceinline__ u64t add2(u64t a, u64t b) {
    u64t d;
    asm("add.rn.f32x2 %0, %1, %2;" : "=l"(d) : "l"(a), "l"(b));
    return d;
}

__device__ __forceinline__ void cvt_store(uint32_t* hi, uint32_t* lo, int idx, float4 v) {
    uint32_t h0 = f2tf(v.x), h1 = f2tf(v.y), h2 = f2tf(v.z), h3 = f2tf(v.w);
    uint32_t l0 = f2tf(v.x - __uint_as_float(h0));
    uint32_t l1 = f2tf(v.y - __uint_as_float(h1));
    uint32_t l2 = f2tf(v.z - __uint_as_float(h2));
    uint32_t l3 = f2tf(v.w - __uint_as_float(h3));
    *(uint4*)&hi[idx] = make_uint4(h0, h1, h2, h3);
    *(uint4*)&lo[idx] = make_uint4(l0, l1, l2, l3);
}

// ---------------- core: C(128x64 tile) = X @ W^T, 3xTF32 ----------------
#define SMS 36
#define GEMM_SMEM_BYTES (13824 * 4)

__device__ __forceinline__ void gemm_core(
    uint32_t* __restrict__ smw,
    const float* __restrict__ X, int ldx,
    const float* __restrict__ W, int ldw,
    float* __restrict__ C, int ldc,
    int K, int m0, int n0)
{
    uint32_t* sAh = smw;
    uint32_t* sAl = smw + 4608;
    uint32_t* sWh = smw + 9216;
    uint32_t* sWl = smw + 11520;

    int tid = threadIdx.x;
    int row0 = tid >> 3, col4 = (tid & 7) * 4;
    const float* Xp = X + (long)(m0 + row0) * ldx + col4;
    const float* Wp = W + (long)(n0 + row0) * ldw + col4;

    float4 xa[4], wa[2];
#pragma unroll
    for (int r = 0; r < 4; ++r) xa[r] = *(const float4*)(Xp + (long)(32 * r) * ldx);
#pragma unroll
    for (int r = 0; r < 2; ++r) wa[r] = *(const float4*)(Wp + (long)(32 * r) * ldw);

    int lane = tid & 31, wrp = tid >> 5;
    int gid = lane >> 2, tig = lane & 3;
    int wm = wrp >> 1, wn = wrp & 1;

    float acc[2][4][4];
#pragma unroll
    for (int ms = 0; ms < 2; ++ms)
#pragma unroll
        for (int t = 0; t < 4; ++t)
#pragma unroll
            for (int i = 0; i < 4; ++i) acc[ms][t][i] = 0.f;

    for (int k0 = 0; k0 < K; k0 += 32) {
#pragma unroll
        for (int r = 0; r < 4; ++r)
            cvt_store(sAh, sAl, (row0 + 32 * r) * SMS + col4, xa[r]);
#pragma unroll
        for (int r = 0; r < 2; ++r)
            cvt_store(sWh, sWl, (row0 + 32 * r) * SMS + col4, wa[r]);
        __syncthreads();
        if (k0 + 32 < K) {
#pragma unroll
            for (int r = 0; r < 4; ++r)
                xa[r] = *(const float4*)(Xp + (long)(32 * r) * ldx + k0 + 32);
#pragma unroll
            for (int r = 0; r < 2; ++r)
                wa[r] = *(const float4*)(Wp + (long)(32 * r) * ldw + k0 + 32);
        }
#pragma unroll
        for (int ks = 0; ks < 4; ++ks) {
            int kk = ks * 8;
            uint32_t ah[2][4], al[2][4];
#pragma unroll
            for (int ms = 0; ms < 2; ++ms) {
                int am = wm * 32 + ms * 16 + gid;
                int ia0 = am * SMS + kk + tig;
                int ia1 = (am + 8) * SMS + kk + tig;
                ah[ms][0] = sAh[ia0]; ah[ms][1] = sAh[ia1];
                ah[ms][2] = sAh[ia0 + 4]; ah[ms][3] = sAh[ia1 + 4];
                al[ms][0] = sAl[ia0]; al[ms][1] = sAl[ia1];
                al[ms][2] = sAl[ia0 + 4]; al[ms][3] = sAl[ia1 + 4];
            }
#pragma unroll
            for (int t = 0; t < 4; ++t) {
                int nn = (wn * 32 + t * 8 + gid) * SMS + kk + tig;
                uint32_t bh0 = sWh[nn], bh1 = sWh[nn + 4];
                uint32_t bl0 = sWl[nn], bl1 = sWl[nn + 4];
#pragma unroll
                for (int ms = 0; ms < 2; ++ms) {
                    mma_tf32(acc[ms][t][0], acc[ms][t][1], acc[ms][t][2], acc[ms][t][3],
                             ah[ms][0], ah[ms][1], ah[ms][2], ah[ms][3], bh0, bh1);
                    mma_tf32(acc[ms][t][0], acc[ms][t][1], acc[ms][t][2], acc[ms][t][3],
                             ah[ms][0], ah[ms][1], ah[ms][2], ah[ms][3], bl0, bl1);
                    mma_tf32(acc[ms][t][0], acc[ms][t][1], acc[ms][t][2], acc[ms][t][3],
                             al[ms][0], al[ms][1], al[ms][2], al[ms][3], bh0, bh1);
                }
            }
        }
        __syncthreads();
    }

#pragma unroll
    for (int ms = 0; ms < 2; ++ms) {
#pragma unroll
        for (int t = 0; t < 4; ++t) {
            int cn = n0 + wn * 32 + t * 8 + tig * 2;
            long r1 = (long)(m0 + wm * 32 + ms * 16 + gid) * ldc + cn;
            *(float2*)&C[r1] = make_float2(acc[ms][t][0], acc[ms][t][1]);
            *(float2*)&C[r1 + 8 * (long)ldc] = make_float2(acc[ms][t][2], acc[ms][t][3]);
        }
    }
}

// ---------------- fused 4-way projection launch ----------------
__global__ __launch_bounds__(256) void proj4(
    const float* __restrict__ q, const float* __restrict__ k,
    const float* __restrict__ v, const float* __restrict__ qu,
    const float* __restrict__ wq, const float* __restrict__ wk,
    const float* __restrict__ wv, const float* __restrict__ wu,
    float* __restrict__ pq, float* __restrict__ pk,
    float* __restrict__ pv, float* __restrict__ pu)
{
    extern __shared__ uint32_t dsm_p[];
    int z = blockIdx.z;
    const float* X; const float* W; float* C; int M;
    if (z == 0)      { X = q;  W = wq; C = pq; M = B_ * LK_; }
    else if (z == 1) { X = k;  W = wk; C = pk; M = B_ * LK_; }
    else if (z == 2) { X = v;  W = wv; C = pv; M = B_ * LK_; }
    else             { X = qu; W = wu; C = pu; M = B_ * NQ_; }
    int m0 = blockIdx.y * 128;
    if (m0 >= M) return;
    gemm_core(dsm_p, X, DM_, W, DM_, C, DM_, DM_, m0, blockIdx.x * 64);
}

// ---------------- A = OUT @ fc_w^T (K=512) ----------------
__global__ __launch_bounds__(256) void gemm_a(
    const float* __restrict__ OUT, const float* __restrict__ fcw,
    float* __restrict__ A)
{
    extern __shared__ uint32_t dsm_a[];
    gemm_core(dsm_a, OUT, DM_, fcw, DM_, A, DM_, DM_,
              blockIdx.y * 128, blockIdx.x * 64);
}

// ---------------- VF[h] = PV_h @ fc_w_h^T (K=64), z = h ----------------
__global__ __launch_bounds__(256) void gemm_vf(
    const float* __restrict__ PV, const float* __restrict__ fcw,
    float* __restrict__ VF)
{
    extern __shared__ uint32_t dsm_v[];
    int h = blockIdx.z;
    gemm_core(dsm_v, PV + h * 64, DM_, fcw + h * 64, DM_,
              VF + (long)h * (B_ * LK_ * DM_), DM_, 64,
              blockIdx.y * 128, blockIdx.x * 64);
}

// ---------------- fused self-attention: softmax(QK^T/8) @ V ----------------
// 512 threads: each (q-row, k-quarter) pair handled by TWO adjacent lanes,
// each owning 32 of the 64 d-elements (halves per-thread state; partner dot
// combined via shfl_xor(1)).
__global__ __launch_bounds__(512) void attn_self(
    const float* __restrict__ PQ, const float* __restrict__ PK,
    const float* __restrict__ PV, float* __restrict__ OUT)
{
    extern __shared__ float sm[];
    float* Ks = sm;
    float* Vs = sm + 16384;

    int h = blockIdx.z, b = blockIdx.y, q0 = blockIdx.x * 64;
    int tid = threadIdx.x;
    long kvbase = ((long)b * LK_) * DM_ + h * 64;

    for (int e = tid; e < 16384; e += 512) {
        int j = e >> 6, d = e & 63;
        Ks[e] = PK[kvbase + (long)j * DM_ + d];
        Vs[e] = PV[kvbase + (long)j * DM_ + d];
    }

    int lane = tid & 31, wrp = tid >> 5;
    int dh = lane & 1;                   // d-half: 0 -> d[0:32), 1 -> d[32:64)
    int idx = wrp * 16 + (lane >> 1);    // 0..255 = (row, quarter)
    int row = idx & 63, qr = idx >> 6;
    int d0 = dh * 32;

    u64t q2[16];
    {
        const float4* qp = (const float4*)(PQ + kvbase + (long)(q0 + row) * DM_ + d0);
#pragma unroll
        for (int i = 0; i < 8; ++i) {
            float4 t = qp[i];
            q2[2 * i] = pk2(t.x, t.y);
            q2[2 * i + 1] = pk2(t.z, t.w);
        }
    }
    __syncthreads();

    float m = -1e30f, l = 0.f;
    u64t av[16];
#pragma unroll
    for (int i = 0; i < 16; ++i) av[i] = 0ull;

    int jbase = qr * 64;
    for (int jc = 0; jc < 64; jc += 8) {
        float s[8];
#pragma unroll
        for (int jj = 0; jj < 8; ++jj) {
            const ulonglong2* kp = (const ulonglong2*)(Ks + (jbase + jc + jj) * 64 + d0);
            u64t a2a = 0ull, a2b = 0ull;
#pragma unroll
            for (int i = 0; i < 8; ++i) {
                ulonglong2 kk2 = kp[i];
                a2a = fma2(q2[2 * i], kk2.x, a2a);
                a2b = fma2(q2[2 * i + 1], kk2.y, a2b);
            }
            float ax, ay, bx, by;
            upk2(a2a, ax, ay);
            upk2(a2b, bx, by);
            float part = ax + ay + bx + by;
            part += __shfl_xor_sync(0xffffffffu, part, 1);
            s[jj] = part * 0.125f;
        }
        float cm = s[0];
#pragma unroll
        for (int jj = 1; jj < 8; ++jj) cm = fmaxf(cm, s[jj]);
        float nm = fmaxf(m, cm);
        float r = __expf(m - nm);
        l *= r;
        u64t rr = pk2(r, r);
#pragma unroll
        for (int i = 0; i < 16; ++i) av[i] = mul2(av[i], rr);
        m = nm;
#pragma unroll
        for (int jj = 0; jj < 8; ++jj) {
            float p = __expf(s[jj] - m);
            l += p;
            u64t pp = pk2(p, p);
            const ulonglong2* vp = (const ulonglong2*)(Vs + (jbase + jc + jj) * 64 + d0);
#pragma unroll
            for (int i = 0; i < 8; ++i) {
                ulonglong2 vv = vp[i];
                av[2 * i] = fma2(vv.x, pp, av[2 * i]);
                av[2 * i + 1] = fma2(vv.y, pp, av[2 * i + 1]);
            }
        }
    }
    __syncthreads();  // Ks/Vs dead; reuse for reduction

    float* mbuf = Vs;          // [row*4+qr] (partner lanes write same value)
    float* lbuf = Vs + 256;
    mbuf[row * 4 + qr] = m;
    __syncthreads();
    float M = fmaxf(fmaxf(mbuf[row * 4 + 0], mbuf[row * 4 + 1]),
                    fmaxf(mbuf[row * 4 + 2], mbuf[row * 4 + 3]));
    float f = __expf(m - M);
    lbuf[row * 4 + qr] = l * f;
    float* obuf = Ks + (qr * 64 + row) * 64 + d0;
    u64t ff = pk2(f, f);
#pragma unroll
    for (int i = 0; i < 16; ++i) {
        u64t sc = mul2(av[i], ff);
        float f0, f1;
        upk2(sc, f0, f1);
        *(float2*)&obuf[2 * i] = make_float2(f0, f1);
    }
    __syncthreads();

    // Output: 512 threads, each handles 8 d's of one row
    int row2 = tid & 63, seg = tid >> 6;     // seg 0..7
    int d2 = seg * 8;
    float L = lbuf[row2 * 4 + 0] + lbuf[row2 * 4 + 1] +
              lbuf[row2 * 4 + 2] + lbuf[row2 * 4 + 3];
    float invL = 1.f / L;

    float* op = OUT + kvbase + (long)(q0 + row2) * DM_;
#pragma unroll
    for (int dd = 0; dd < 8; dd += 4) {
        int d = d2 + dd;
        float4 t0 = *(const float4*)&Ks[(0 * 64 + row2) * 64 + d];
        float4 t1 = *(const float4*)&Ks[(1 * 64 + row2) * 64 + d];
        float4 t2 = *(const float4*)&Ks[(2 * 64 + row2) * 64 + d];
        float4 t3 = *(const float4*)&Ks[(3 * 64 + row2) * 64 + d];
        float4 o;
        o.x = (t0.x + t1.x + t2.x + t3.x) * invL;
        o.y = (t0.y + t1.y + t2.y + t3.y) * invL;
        o.z = (t0.z + t1.z + t2.z + t3.z) * invL;
        o.w = (t0.w + t1.w + t2.w + t3.w) * invL;
        *(float4*)(op + d) = o;
    }
}

// ---------------- query attention probs: softmax(QU K^T/8), transposed out ----------------
__global__ __launch_bounds__(256) void attn_query(
    const float* __restrict__ PU, const float* __restrict__ PK,
    float* __restrict__ QT)
{
    extern __shared__ float sm[];
    float* Ks = sm;
    float* Ss = sm + 16384;
    float* red = Ss + 64 * 260;

    int b = blockIdx.x, h = blockIdx.y;
    int tid = threadIdx.x;
    long kvbase = ((long)b * LK_) * DM_ + h * 64;

    for (int e = tid; e < 16384; e += 256) {
        int j = e >> 6, d = e & 63;
        Ks[e] = PK[kvbase + (long)j * DM_ + d];
    }

    int n = tid >> 2, qr = tid & 3;
    float qv[64];
    {
        const float* qp = PU + ((long)(b * NQ_ + n)) * DM_ + h * 64;
#pragma unroll
        for (int d = 0; d < 64; d += 4) {
            float4 t = *(const float4*)(qp + d);
            qv[d] = t.x; qv[d + 1] = t.y; qv[d + 2] = t.z; qv[d + 3] = t.w;
        }
    }
    __syncthreads();

    float* srow = Ss + n * 260;
    float lm = -1e30f;
    for (int k = qr * 64; k < qr * 64 + 64; ++k) {
        const float* kp = Ks + k * 64;
        float a = 0.f;
#pragma unroll
        for (int d = 0; d < 64; d += 4) {
            float4 k4 = *(const float4*)(kp + d);
            a += qv[d] * k4.x + qv[d + 1] * k4.y + qv[d + 2] * k4.z + qv[d + 3] * k4.w;
        }
        float sv = a * 0.125f;
        srow[k] = sv;
        lm = fmaxf(lm, sv);
    }
    red[n * 4 + qr] = lm;
    __syncthreads();
    float M = fmaxf(fmaxf(red[n * 4 + 0], red[n * 4 + 1]),
                    fmaxf(red[n * 4 + 2], red[n * 4 + 3]));
    float es = 0.f;
    for (int k = qr * 64; k < qr * 64 + 64; ++k) es += __expf(srow[k] - M);
    red[256 + n * 4 + qr] = es;
    __syncthreads();
    float S = red[256 + n * 4 + 0] + red[256 + n * 4 + 1] +
              red[256 + n * 4 + 2] + red[256 + n * 4 + 3];
    float inv = 1.f / S;
    for (int k = qr * 64; k < qr * 64 + 64; ++k) {
        float p = __expf(srow[k] - M) * inv;
        QT[((long)(b * LK_ + k) * NQ_ + n) * 8 + h] = p;
    }
}

// ---------------- LN stats (analytic quadratic form) -> g_MU/g_RS ----------------
__global__ __launch_bounds__(256) void combine_stats(
    const float* __restrict__ VF, const float* __restrict__ A,
    const float* __restrict__ QT, const float* __restrict__ qin,
    const float* __restrict__ fc_b,
    float* __restrict__ MU, float* __restrict__ RS)
{
    __shared__ float qt[512];
    __shared__ float red[54 * 8];
    __shared__ float S[54];

    int k = blockIdx.x, b = blockIdx.y;
    long rk = (long)b * LK_ + k;
    int tid = threadIdx.x, lane = tid & 31, wid = tid >> 5;

    float2 vf[8];
#pragma unroll
    for (int h = 0; h < 8; ++h)
        vf[h] = ((const float2*)(VF + (long)h * (B_ * LK_ * DM_) + rk * DM_))[tid];
    float2 bb = ((const float2*)(A + rk * DM_))[tid];
    float2 qv = ((const float2*)(qin + rk * DM_))[tid];
    float2 fb = ((const float2*)fc_b)[tid];
    bb.x += qv.x + fb.x; bb.y += qv.y + fb.y;
    for (int e = tid; e < 512; e += 256) qt[e] = QT[rk * 512 + e];

    float part[54];
    part[0] = bb.x + bb.y;
#pragma unroll
    for (int h = 0; h < 8; ++h) part[1 + h] = vf[h].x + vf[h].y;
    part[9] = bb.x * bb.x + bb.y * bb.y;
#pragma unroll
    for (int h = 0; h < 8; ++h) part[10 + h] = bb.x * vf[h].x + bb.y * vf[h].y;
    {
        int c = 18;
#pragma unroll
        for (int h = 0; h < 8; ++h)
#pragma unroll
            for (int h2 = h; h2 < 8; ++h2)
                part[c++] = vf[h].x * vf[h2].x + vf[h].y * vf[h2].y;
    }
#pragma unroll
    for (int i = 0; i < 54; ++i) {
#pragma unroll
        for (int o = 16; o; o >>= 1)
            part[i] += __shfl_down_sync(0xffffffffu, part[i], o);
    }
    if (lane == 0) {
#pragma unroll
        for (int i = 0; i < 54; ++i) red[i * 8 + wid] = part[i];
    }
    __syncthreads();
    if (tid < 54) {
        float s = 0.f;
#pragma unroll
        for (int w = 0; w < 8; ++w) s += red[tid * 8 + w];
        S[tid] = s;
    }
    __syncthreads();
    if (tid < 64) {
        float g[8];
#pragma unroll
        for (int h = 0; h < 8; ++h) g[h] = qt[tid * 8 + h];
        float sum = S[0];
        float sq = S[9];
#pragma unroll
        for (int h = 0; h < 8; ++h) {
            sum += g[h] * S[1 + h];
            sq += 2.f * g[h] * S[10 + h];
        }
        int c = 18;
#pragma unroll
        for (int h = 0; h < 8; ++h)
#pragma unroll
            for (int h2 = h; h2 < 8; ++h2) {
                float co = (h == h2) ? g[h] * g[h] : 2.f * g[h] * g[h2];
                sq += co * S[c++];
            }
        float mu = sum * (1.f / 512.f);
        float var = sq * (1.f / 512.f) - mu * mu;
        MU[rk * 64 + tid] = mu;
        RS[rk * 64 + tid] = rsqrtf(var + 1e-5f);
    }
}

// ---------------- streaming combine epilogue (f32x2): rank-8 update + LN apply ----------------
__global__ __launch_bounds__(256) void combine_stream(
    const float* __restrict__ VF, const float* __restrict__ A,
    const float* __restrict__ QT, const float* __restrict__ qin,
    const float* __restrict__ fc_b, const float* __restrict__ ln_w,
    const float* __restrict__ ln_b, const float* __restrict__ MU,
    const float* __restrict__ RS, float* __restrict__ out)
{
    __shared__ float qt[2][512];
    __shared__ float mus[2][64], rss[2][64];

    int k0 = blockIdx.x * 2, b = blockIdx.y;
    int tid = threadIdx.x;
    int half = tid >> 7, t = tid & 127;
    long rk = (long)b * LK_ + k0 + half;
    int c4 = t * 4;

    u64t vfa[8], vfb[8];
#pragma unroll
    for (int h = 0; h < 8; ++h) {
        ulonglong2 tt = *(const ulonglong2*)(VF + (long)h * (B_ * LK_ * DM_) + rk * DM_ + c4);
        vfa[h] = tt.x; vfb[h] = tt.y;
    }
    float4 bb = *(const float4*)(A + rk * DM_ + c4);
    {
        float4 qv = *(const float4*)(qin + rk * DM_ + c4);
        float4 fb = *(const float4*)(fc_b + c4);
        bb.x += qv.x + fb.x; bb.y += qv.y + fb.y;
        bb.z += qv.z + fb.z; bb.w += qv.w + fb.w;
    }
    u64t b2a = pk2(bb.x, bb.y), b2b = pk2(bb.z, bb.w);
    float4 lw = *(const float4*)(ln_w + c4);
    float4 lb = *(const float4*)(ln_b + c4);
    u64t lw2a = pk2(lw.x, lw.y), lw2b = pk2(lw.z, lw.w);
    u64t lb2a = pk2(lb.x, lb.y), lb2b = pk2(lb.z, lb.w);

    *(float4*)&qt[half][c4] = *(const float4*)(QT + rk * 512 + c4);
    if (t < 64) {
        mus[half][t] = MU[rk * 64 + t];
        rss[half][t] = RS[rk * 64 + t];
    }
    __syncthreads();

    long obase = (long)b * (NQ_ * LK_ * DM_) + (long)(k0 + half) * DM_ + c4;
    const float* qtr = qt[half];
#pragma unroll 4
    for (int n = 0; n < NQ_; ++n) {
        u64t v0 = b2a, v1 = b2b;
#pragma unroll
        for (int h = 0; h < 8; ++h) {
            float g = qtr[n * 8 + h];
            u64t g2 = pk2(g, g);
            v0 = fma2(vfa[h], g2, v0);
            v1 = fma2(vfb[h], g2, v1);
        }
        float mu = mus[half][n], rs = rss[half][n];
        u64t nm2 = pk2(-mu, -mu), rs2 = pk2(rs, rs);
        u64t o0 = fma2(mul2(add2(v0, nm2), rs2), lw2a, lb2a);
        u64t o1 = fma2(mul2(add2(v1, nm2), rs2), lw2b, lb2b);
        ulonglong2 st;
        st.x = o0; st.y = o1;
        *(ulonglong2*)(out + obase + (long)n * (LK_ * DM_)) = st;
    }
}

// ---------------- host launcher (stream-forked DAG with serial fallback) ----------------
extern "C" void kernel_launch(void* const* d_in, const int* in_sizes, int n_in,
                              void* d_out, int out_size)
{
    (void)in_sizes; (void)n_in; (void)out_size;
    const float* q     = (const float*)d_in[0];
    const float* k     = (const float*)d_in[1];
    const float* v     = (const float*)d_in[2];
    const float* query = (const float*)d_in[3];
    const float* w_qs  = (const float*)d_in[4];
    const float* w_ks  = (const float*)d_in[5];
    const float* w_vs  = (const float*)d_in[6];
    const float* w_qu  = (const float*)d_in[7];
    const float* fc_w  = (const float*)d_in[8];
    const float* fc_b  = (const float*)d_in[9];
    const float* ln_w  = (const float*)d_in[10];
    const float* ln_b  = (const float*)d_in[11];
    float* out = (float*)d_out;

    float *pPQ, *pPK, *pPV, *pPU, *pOUT, *pA, *pQT, *pVF, *pMU, *pRS;
    cudaGetSymbolAddress((void**)&pPQ,  g_PQ);
    cudaGetSymbolAddress((void**)&pPK,  g_PK);
    cudaGetSymbolAddress((void**)&pPV,  g_PV);
    cudaGetSymbolAddress((void**)&pPU,  g_PU);
    cudaGetSymbolAddress((void**)&pOUT, g_OUT);
    cudaGetSymbolAddress((void**)&pA,   g_A);
    cudaGetSymbolAddress((void**)&pQT,  g_QT);
    cudaGetSymbolAddress((void**)&pVF,  g_VF);
    cudaGetSymbolAddress((void**)&pMU,  g_MU);
    cudaGetSymbolAddress((void**)&pRS,  g_RS);

    static bool init_done = false;
    static bool streams_ok = false;
    static cudaStream_t s1 = nullptr, s2 = nullptr;
    static cudaEvent_t evP = nullptr, ev1 = nullptr, ev2 = nullptr;
    if (!init_done) {
        init_done = true;
        cudaFuncSetAttribute(proj4,    cudaFuncAttributeMaxDynamicSharedMemorySize, GEMM_SMEM_BYTES);
        cudaFuncSetAttribute(gemm_a,   cudaFuncAttributeMaxDynamicSharedMemorySize, GEMM_SMEM_BYTES);
        cudaFuncSetAttribute(gemm_vf,  cudaFuncAttributeMaxDynamicSharedMemorySize, GEMM_SMEM_BYTES);
        cudaFuncSetAttribute(attn_self, cudaFuncAttributeMaxDynamicSharedMemorySize, 2 * 16384 * 4);
        cudaFuncSetAttribute(attn_query, cudaFuncAttributeMaxDynamicSharedMemorySize,
                             (16384 + 64 * 260 + 512) * 4);
        bool ok = true;
        ok = ok && (cudaStreamCreateWithFlags(&s1, cudaStreamNonBlocking) == cudaSuccess);
        ok = ok && (cudaStreamCreateWithFlags(&s2, cudaStreamNonBlocking) == cudaSuccess);
        ok = ok && (cudaEventCreateWithFlags(&evP, cudaEventDisableTiming) == cudaSuccess);
        ok = ok && (cudaEventCreateWithFlags(&ev1, cudaEventDisableTiming) == cudaSuccess);
        ok = ok && (cudaEventCreateWithFlags(&ev2, cudaEventDisableTiming) == cudaSuccess);
        streams_ok = ok;
    }

    dim3 thr(256);

    // Stage 1: projections (default stream)
    proj4<<<dim3(8, 8, 4), thr, GEMM_SMEM_BYTES>>>(q, k, v, query, w_qs, w_ks, w_vs, w_qu,
                                                   pPQ, pPK, pPV, pPU);

    if (streams_ok) {
        cudaEventRecord(evP, 0);
        cudaStreamWaitEvent(s1, evP, 0);
        cudaStreamWaitEvent(s2, evP, 0);

        gemm_vf<<<dim3(8, 8, 8), thr, GEMM_SMEM_BYTES, s1>>>(pPV, fc_w, pVF);
        attn_query<<<dim3(B_, H_), thr, (16384 + 64 * 260 + 512) * 4, s2>>>(pPU, pPK, pQT);

        attn_self<<<dim3(4, B_, H_), dim3(512), 2 * 16384 * 4>>>(pPQ, pPK, pPV, pOUT);
        gemm_a<<<dim3(8, 8), thr, GEMM_SMEM_BYTES>>>(pOUT, fc_w, pA);

        cudaEventRecord(ev1, s1);
        cudaEventRecord(ev2, s2);
        cudaStreamWaitEvent(0, ev1, 0);
        cudaStreamWaitEvent(0, ev2, 0);
    } else {
        attn_self<<<dim3(4, B_, H_), dim3(512), 2 * 16384 * 4>>>(pPQ, pPK, pPV, pOUT);
        attn_query<<<dim3(B_, H_), thr, (16384 + 64 * 260 + 512) * 4>>>(pPU, pPK, pQT);
        gemm_vf<<<dim3(8, 8, 8), thr, GEMM_SMEM_BYTES>>>(pPV, fc_w, pVF);
        gemm_a<<<dim3(8, 8), thr, GEMM_SMEM_BYTES>>>(pOUT, fc_w, pA);
    }

    // Stage 3: LN stats then streaming epilogue (default stream)
    combine_stats<<<dim3(LK_, B_), thr>>>(pVF, pA, pQT, q, fc_b, pMU, pRS);
    combine_stream<<<dim3(LK_ / 2, B_), thr>>>(pVF, pA, pQT, q, fc_b, ln_w, ln_b,
                                               pMU, pRS, out);
}

// round 13
// speedup vs baseline: 1.1295x; 1.1295x over previous
#include <cuda_runtime.h>
#include <cuda_bf16.h>
#include <cstdint>

// Shapes (fixed): B=4, LK=256, NQ=64, H=8, DK=DV=64, DM=512
#define B_ 4
#define LK_ 256
#define NQ_ 64
#define H_ 8
#define DM_ 512

// ---------------- scratch (device globals; no allocation) ----------------
__device__ float g_PQ[B_ * LK_ * DM_];
__device__ float g_PK[B_ * LK_ * DM_];
__device__ float g_PV[B_ * LK_ * DM_];
__device__ float g_PU[B_ * NQ_ * DM_];
__device__ float g_OUT[B_ * LK_ * DM_];
__device__ float g_A[B_ * LK_ * DM_];
__device__ float g_QT[B_ * LK_ * NQ_ * H_];
__device__ float g_VF[H_ * B_ * LK_ * DM_];
__device__ float g_MU[B_ * LK_ * NQ_];
__device__ float g_RS[B_ * LK_ * NQ_];

// ---------------- tf32 + f32x2 helpers ----------------
__device__ __forceinline__ uint32_t f2tf(float x) {
    uint32_t r;
    asm("cvt.rna.tf32.f32 %0, %1;" : "=r"(r) : "f"(x));
    return r;
}

__device__ __forceinline__ void mma_tf32(
    float& c0, float& c1, float& c2, float& c3,
    uint32_t a0, uint32_t a1, uint32_t a2, uint32_t a3,
    uint32_t b0, uint32_t b1)
{
    asm volatile(
        "mma.sync.aligned.m16n8k8.row.col.f32.tf32.tf32.f32 "
        "{%0,%1,%2,%3},{%4,%5,%6,%7},{%8,%9},{%0,%1,%2,%3};"
        : "+f"(c0), "+f"(c1), "+f"(c2), "+f"(c3)
        : "r"(a0), "r"(a1), "r"(a2), "r"(a3), "r"(b0), "r"(b1));
}

typedef unsigned long long u64t;

__device__ __forceinline__ u64t pk2(float lo, float hi) {
    u64t r;
    asm("mov.b64 %0, {%1, %2};" : "=l"(r) : "f"(lo), "f"(hi));
    return r;
}
__device__ __forceinline__ void upk2(u64t v, float& lo, float& hi) {
    asm("mov.b64 {%0, %1}, %2;" : "=f"(lo), "=f"(hi) : "l"(v));
}
__device__ __forceinline__ u64t fma2(u64t a, u64t b, u64t c) {
    u64t d;
    asm("fma.rn.f32x2 %0, %1, %2, %3;" : "=l"(d) : "l"(a), "l"(b), "l"(c));
    return d;
}
__device__ __forceinline__ u64t mul2(u64t a, u64t b) {
    u64t d;
    asm("mul.rn.f32x2 %0, %1, %2;" : "=l"(d) : "l"(a), "l"(b));
    return d;
}
__device__ __forceinline__ u64t add2(u64t a, u64t b) {
    u64t d;
    asm("add.rn.f32x2 %0, %1, %2;" : "=l"(d) : "l"(a), "l"(b));
    return d;
}

__device__ __forceinline__ void cvt_store(uint32_t* hi, uint32_t* lo, int idx, float4 v) {
    uint32_t h0 = f2tf(v.x), h1 = f2tf(v.y), h2 = f2tf(v.z), h3 = f2tf(v.w);
    uint32_t l0 = f2tf(v.x - __uint_as_float(h0));
    uint32_t l1 = f2tf(v.y - __uint_as_float(h1));
    uint32_t l2 = f2tf(v.z - __uint_as_float(h2));
    uint32_t l3 = f2tf(v.w - __uint_as_float(h3));
    *(uint4*)&hi[idx] = make_uint4(h0, h1, h2, h3);
    *(uint4*)&lo[idx] = make_uint4(l0, l1, l2, l3);
}

// ---------------- core: C(128x64 tile) = X @ W^T, 3xTF32 ----------------
#define SMS 36
#define GEMM_SMEM_BYTES (13824 * 4)

__device__ __forceinline__ void gemm_core(
    uint32_t* __restrict__ smw,
    const float* __restrict__ X, int ldx,
    const float* __restrict__ W, int ldw,
    float* __restrict__ C, int ldc,
    int K, int m0, int n0)
{
    uint32_t* sAh = smw;
    uint32_t* sAl = smw + 4608;
    uint32_t* sWh = smw + 9216;
    uint32_t* sWl = smw + 11520;

    int tid = threadIdx.x;
    int row0 = tid >> 3, col4 = (tid & 7) * 4;
    const float* Xp = X + (long)(m0 + row0) * ldx + col4;
    const float* Wp = W + (long)(n0 + row0) * ldw + col4;

    float4 xa[4], wa[2];
#pragma unroll
    for (int r = 0; r < 4; ++r) xa[r] = *(const float4*)(Xp + (long)(32 * r) * ldx);
#pragma unroll
    for (int r = 0; r < 2; ++r) wa[r] = *(const float4*)(Wp + (long)(32 * r) * ldw);

    int lane = tid & 31, wrp = tid >> 5;
    int gid = lane >> 2, tig = lane & 3;
    int wm = wrp >> 1, wn = wrp & 1;

    float acc[2][4][4];
#pragma unroll
    for (int ms = 0; ms < 2; ++ms)
#pragma unroll
        for (int t = 0; t < 4; ++t)
#pragma unroll
            for (int i = 0; i < 4; ++i) acc[ms][t][i] = 0.f;

    for (int k0 = 0; k0 < K; k0 += 32) {
#pragma unroll
        for (int r = 0; r < 4; ++r)
            cvt_store(sAh, sAl, (row0 + 32 * r) * SMS + col4, xa[r]);
#pragma unroll
        for (int r = 0; r < 2; ++r)
            cvt_store(sWh, sWl, (row0 + 32 * r) * SMS + col4, wa[r]);
        __syncthreads();
        if (k0 + 32 < K) {
#pragma unroll
            for (int r = 0; r < 4; ++r)
                xa[r] = *(const float4*)(Xp + (long)(32 * r) * ldx + k0 + 32);
#pragma unroll
            for (int r = 0; r < 2; ++r)
                wa[r] = *(const float4*)(Wp + (long)(32 * r) * ldw + k0 + 32);
        }
#pragma unroll
        for (int ks = 0; ks < 4; ++ks) {
            int kk = ks * 8;
            uint32_t ah[2][4], al[2][4];
#pragma unroll
            for (int ms = 0; ms < 2; ++ms) {
                int am = wm * 32 + ms * 16 + gid;
                int ia0 = am * SMS + kk + tig;
                int ia1 = (am + 8) * SMS + kk + tig;
                ah[ms][0] = sAh[ia0]; ah[ms][1] = sAh[ia1];
                ah[ms][2] = sAh[ia0 + 4]; ah[ms][3] = sAh[ia1 + 4];
                al[ms][0] = sAl[ia0]; al[ms][1] = sAl[ia1];
                al[ms][2] = sAl[ia0 + 4]; al[ms][3] = sAl[ia1 + 4];
            }
#pragma unroll
            for (int t = 0; t < 4; ++t) {
                int nn = (wn * 32 + t * 8 + gid) * SMS + kk + tig;
                uint32_t bh0 = sWh[nn], bh1 = sWh[nn + 4];
                uint32_t bl0 = sWl[nn], bl1 = sWl[nn + 4];
#pragma unroll
                for (int ms = 0; ms < 2; ++ms) {
                    mma_tf32(acc[ms][t][0], acc[ms][t][1], acc[ms][t][2], acc[ms][t][3],
                             ah[ms][0], ah[ms][1], ah[ms][2], ah[ms][3], bh0, bh1);
                    mma_tf32(acc[ms][t][0], acc[ms][t][1], acc[ms][t][2], acc[ms][t][3],
                             ah[ms][0], ah[ms][1], ah[ms][2], ah[ms][3], bl0, bl1);
                    mma_tf32(acc[ms][t][0], acc[ms][t][1], acc[ms][t][2], acc[ms][t][3],
                             al[ms][0], al[ms][1], al[ms][2], al[ms][3], bh0, bh1);
                }
            }
        }
        __syncthreads();
    }

#pragma unroll
    for (int ms = 0; ms < 2; ++ms) {
#pragma unroll
        for (int t = 0; t < 4; ++t) {
            int cn = n0 + wn * 32 + t * 8 + tig * 2;
            long r1 = (long)(m0 + wm * 32 + ms * 16 + gid) * ldc + cn;
            *(float2*)&C[r1] = make_float2(acc[ms][t][0], acc[ms][t][1]);
            *(float2*)&C[r1 + 8 * (long)ldc] = make_float2(acc[ms][t][2], acc[ms][t][3]);
        }
    }
}

// ---------------- fused 4-way projection launch ----------------
__global__ __launch_bounds__(256) void proj4(
    const float* __restrict__ q, const float* __restrict__ k,
    const float* __restrict__ v, const float* __restrict__ qu,
    const float* __restrict__ wq, const float* __restrict__ wk,
    const float* __restrict__ wv, const float* __restrict__ wu,
    float* __restrict__ pq, float* __restrict__ pk,
    float* __restrict__ pv, float* __restrict__ pu)
{
    extern __shared__ uint32_t dsm_p[];
    int z = blockIdx.z;
    const float* X; const float* W; float* C; int M;
    if (z == 0)      { X = q;  W = wq; C = pq; M = B_ * LK_; }
    else if (z == 1) { X = k;  W = wk; C = pk; M = B_ * LK_; }
    else if (z == 2) { X = v;  W = wv; C = pv; M = B_ * LK_; }
    else             { X = qu; W = wu; C = pu; M = B_ * NQ_; }
    int m0 = blockIdx.y * 128;
    if (m0 >= M) return;
    gemm_core(dsm_p, X, DM_, W, DM_, C, DM_, DM_, m0, blockIdx.x * 64);
}

// ---------------- A = OUT @ fc_w^T (K=512) ----------------
__global__ __launch_bounds__(256) void gemm_a(
    const float* __restrict__ OUT, const float* __restrict__ fcw,
    float* __restrict__ A)
{
    extern __shared__ uint32_t dsm_a[];
    gemm_core(dsm_a, OUT, DM_, fcw, DM_, A, DM_, DM_,
              blockIdx.y * 128, blockIdx.x * 64);
}

// ---------------- VF[h] = PV_h @ fc_w_h^T (K=64), z = h ----------------
__global__ __launch_bounds__(256) void gemm_vf(
    const float* __restrict__ PV, const float* __restrict__ fcw,
    float* __restrict__ VF)
{
    extern __shared__ uint32_t dsm_v[];
    int h = blockIdx.z;
    gemm_core(dsm_v, PV + h * 64, DM_, fcw + h * 64, DM_,
              VF + (long)h * (B_ * LK_ * DM_), DM_, 64,
              blockIdx.y * 128, blockIdx.x * 64);
}

// ---------------- fused self-attention: softmax(QK^T/8) @ V ----------------
// 256 threads; each thread owns TWO q-rows (rp, rp+32) over one 32-d half.
// Every K/V smem chunk loaded serves both rows -> LDS traffic halved vs R11.
__global__ __launch_bounds__(256) void attn_self(
    const float* __restrict__ PQ, const float* __restrict__ PK,
    const float* __restrict__ PV, float* __restrict__ OUT)
{
    extern __shared__ float sm[];
    float* Ks = sm;
    float* Vs = sm + 16384;

    int h = blockIdx.z, b = blockIdx.y, q0 = blockIdx.x * 64;
    int tid = threadIdx.x;
    long kvbase = ((long)b * LK_) * DM_ + h * 64;

    for (int e = tid; e < 16384; e += 256) {
        int j = e >> 6, d = e & 63;
        Ks[e] = PK[kvbase + (long)j * DM_ + d];
        Vs[e] = PV[kvbase + (long)j * DM_ + d];
    }

    int dh = tid & 1;                 // d-half: 0 -> d[0:32), 1 -> d[32:64)
    int idx = tid >> 1;               // 0..127 = (row-pair, quarter)
    int rp = idx & 31, qr = idx >> 5; // rows rp and rp+32; k-quarter qr
    int d0 = dh * 32;

    u64t q2[2][16];
#pragma unroll
    for (int r = 0; r < 2; ++r) {
        const float4* qp = (const float4*)(PQ + kvbase +
                           (long)(q0 + rp + r * 32) * DM_ + d0);
#pragma unroll
        for (int i = 0; i < 8; ++i) {
            float4 t = qp[i];
            q2[r][2 * i] = pk2(t.x, t.y);
            q2[r][2 * i + 1] = pk2(t.z, t.w);
        }
    }
    __syncthreads();

    float m0v = -1e30f, m1v = -1e30f, l0 = 0.f, l1 = 0.f;
    u64t av[2][16];
#pragma unroll
    for (int r = 0; r < 2; ++r)
#pragma unroll
        for (int i = 0; i < 16; ++i) av[r][i] = 0ull;

    int jbase = qr * 64;
    for (int jc = 0; jc < 64; jc += 8) {
        float s0[8], s1[8];
#pragma unroll
        for (int jj = 0; jj < 8; ++jj) {
            const ulonglong2* kp = (const ulonglong2*)(Ks + (jbase + jc + jj) * 64 + d0);
            u64t a0 = 0ull, b0v = 0ull, a1 = 0ull, b1v = 0ull;
#pragma unroll
            for (int i = 0; i < 8; ++i) {
                ulonglong2 kk2 = kp[i];
                a0  = fma2(q2[0][2 * i],     kk2.x, a0);
                b0v = fma2(q2[0][2 * i + 1], kk2.y, b0v);
                a1  = fma2(q2[1][2 * i],     kk2.x, a1);
                b1v = fma2(q2[1][2 * i + 1], kk2.y, b1v);
            }
            float x0, y0, x1, y1, x2, y2, x3, y3;
            upk2(a0, x0, y0); upk2(b0v, x1, y1);
            upk2(a1, x2, y2); upk2(b1v, x3, y3);
            float p0 = x0 + y0 + x1 + y1;
            float p1 = x2 + y2 + x3 + y3;
            p0 += __shfl_xor_sync(0xffffffffu, p0, 1);
            p1 += __shfl_xor_sync(0xffffffffu, p1, 1);
            s0[jj] = p0 * 0.125f;
            s1[jj] = p1 * 0.125f;
        }
        float cm0 = s0[0], cm1 = s1[0];
#pragma unroll
        for (int jj = 1; jj < 8; ++jj) {
            cm0 = fmaxf(cm0, s0[jj]);
            cm1 = fmaxf(cm1, s1[jj]);
        }
        float nm0 = fmaxf(m0v, cm0), nm1 = fmaxf(m1v, cm1);
        float r0 = __expf(m0v - nm0), r1 = __expf(m1v - nm1);
        l0 *= r0; l1 *= r1;
        u64t rr0 = pk2(r0, r0), rr1 = pk2(r1, r1);
#pragma unroll
        for (int i = 0; i < 16; ++i) {
            av[0][i] = mul2(av[0][i], rr0);
            av[1][i] = mul2(av[1][i], rr1);
        }
        m0v = nm0; m1v = nm1;
#pragma unroll
        for (int jj = 0; jj < 8; ++jj) {
            float p0 = __expf(s0[jj] - m0v);
            float p1 = __expf(s1[jj] - m1v);
            l0 += p0; l1 += p1;
            u64t pp0 = pk2(p0, p0), pp1 = pk2(p1, p1);
            const ulonglong2* vp = (const ulonglong2*)(Vs + (jbase + jc + jj) * 64 + d0);
#pragma unroll
            for (int i = 0; i < 8; ++i) {
                ulonglong2 vv = vp[i];
                av[0][2 * i]     = fma2(vv.x, pp0, av[0][2 * i]);
                av[0][2 * i + 1] = fma2(vv.y, pp0, av[0][2 * i + 1]);
                av[1][2 * i]     = fma2(vv.x, pp1, av[1][2 * i]);
                av[1][2 * i + 1] = fma2(vv.y, pp1, av[1][2 * i + 1]);
            }
        }
    }
    __syncthreads();  // Ks/Vs dead; reuse for reduction

    float* mbuf = Vs;          // [row*4+qr] (partner d-half lanes write same value)
    float* lbuf = Vs + 256;
    mbuf[(rp) * 4 + qr] = m0v;
    mbuf[(rp + 32) * 4 + qr] = m1v;
    __syncthreads();
    float M0 = fmaxf(fmaxf(mbuf[rp * 4 + 0], mbuf[rp * 4 + 1]),
                     fmaxf(mbuf[rp * 4 + 2], mbuf[rp * 4 + 3]));
    float M1 = fmaxf(fmaxf(mbuf[(rp + 32) * 4 + 0], mbuf[(rp + 32) * 4 + 1]),
                     fmaxf(mbuf[(rp + 32) * 4 + 2], mbuf[(rp + 32) * 4 + 3]));
    float f0 = __expf(m0v - M0), f1 = __expf(m1v - M1);
    lbuf[rp * 4 + qr] = l0 * f0;
    lbuf[(rp + 32) * 4 + qr] = l1 * f1;
    {
        u64t ff0 = pk2(f0, f0), ff1 = pk2(f1, f1);
        float* ob0 = Ks + (qr * 64 + rp) * 64 + d0;
        float* ob1 = Ks + (qr * 64 + rp + 32) * 64 + d0;
#pragma unroll
        for (int i = 0; i < 16; ++i) {
            u64t sc0 = mul2(av[0][i], ff0);
            u64t sc1 = mul2(av[1][i], ff1);
            float a0x, a0y, a1x, a1y;
            upk2(sc0, a0x, a0y);
            upk2(sc1, a1x, a1y);
            *(float2*)&ob0[2 * i] = make_float2(a0x, a0y);
            *(float2*)&ob1[2 * i] = make_float2(a1x, a1y);
        }
    }
    __syncthreads();

    // Output: 256 threads, each handles 16 d's of one row
    int row2 = tid & 63, seg = tid >> 6;     // seg 0..3
    int d2 = seg * 16;
    float L = lbuf[row2 * 4 + 0] + lbuf[row2 * 4 + 1] +
              lbuf[row2 * 4 + 2] + lbuf[row2 * 4 + 3];
    float invL = 1.f / L;

    float* op = OUT + kvbase + (long)(q0 + row2) * DM_;
#pragma unroll
    for (int dd = 0; dd < 16; dd += 4) {
        int d = d2 + dd;
        float4 t0 = *(const float4*)&Ks[(0 * 64 + row2) * 64 + d];
        float4 t1 = *(const float4*)&Ks[(1 * 64 + row2) * 64 + d];
        float4 t2 = *(const float4*)&Ks[(2 * 64 + row2) * 64 + d];
        float4 t3 = *(const float4*)&Ks[(3 * 64 + row2) * 64 + d];
        float4 o;
        o.x = (t0.x + t1.x + t2.x + t3.x) * invL;
        o.y = (t0.y + t1.y + t2.y + t3.y) * invL;
        o.z = (t0.z + t1.z + t2.z + t3.z) * invL;
        o.w = (t0.w + t1.w + t2.w + t3.w) * invL;
        *(float4*)(op + d) = o;
    }
}

// ---------------- query attention probs: softmax(QU K^T/8), transposed out ----------------
__global__ __launch_bounds__(256) void attn_query(
    const float* __restrict__ PU, const float* __restrict__ PK,
    float* __restrict__ QT)
{
    extern __shared__ float sm[];
    float* Ks = sm;
    float* Ss = sm + 16384;
    float* red = Ss + 64 * 260;

    int b = blockIdx.x, h = blockIdx.y;
    int tid = threadIdx.x;
    long kvbase = ((long)b * LK_) * DM_ + h * 64;

    for (int e = tid; e < 16384; e += 256) {
        int j = e >> 6, d = e & 63;
        Ks[e] = PK[kvbase + (long)j * DM_ + d];
    }

    int n = tid >> 2, qr = tid & 3;
    float qv[64];
    {
        const float* qp = PU + ((long)(b * NQ_ + n)) * DM_ + h * 64;
#pragma unroll
        for (int d = 0; d < 64; d += 4) {
            float4 t = *(const float4*)(qp + d);
            qv[d] = t.x; qv[d + 1] = t.y; qv[d + 2] = t.z; qv[d + 3] = t.w;
        }
    }
    __syncthreads();

    float* srow = Ss + n * 260;
    float lm = -1e30f;
    for (int k = qr * 64; k < qr * 64 + 64; ++k) {
        const float* kp = Ks + k * 64;
        float a = 0.f;
#pragma unroll
        for (int d = 0; d < 64; d += 4) {
            float4 k4 = *(const float4*)(kp + d);
            a += qv[d] * k4.x + qv[d + 1] * k4.y + qv[d + 2] * k4.z + qv[d + 3] * k4.w;
        }
        float sv = a * 0.125f;
        srow[k] = sv;
        lm = fmaxf(lm, sv);
    }
    red[n * 4 + qr] = lm;
    __syncthreads();
    float M = fmaxf(fmaxf(red[n * 4 + 0], red[n * 4 + 1]),
                    fmaxf(red[n * 4 + 2], red[n * 4 + 3]));
    float es = 0.f;
    for (int k = qr * 64; k < qr * 64 + 64; ++k) es += __expf(srow[k] - M);
    red[256 + n * 4 + qr] = es;
    __syncthreads();
    float S = red[256 + n * 4 + 0] + red[256 + n * 4 + 1] +
              red[256 + n * 4 + 2] + red[256 + n * 4 + 3];
    float inv = 1.f / S;
    for (int k = qr * 64; k < qr * 64 + 64; ++k) {
        float p = __expf(srow[k] - M) * inv;
        QT[((long)(b * LK_ + k) * NQ_ + n) * 8 + h] = p;
    }
}

// ---------------- LN stats (analytic quadratic form) -> g_MU/g_RS ----------------
__global__ __launch_bounds__(256) void combine_stats(
    const float* __restrict__ VF, const float* __restrict__ A,
    const float* __restrict__ QT, const float* __restrict__ qin,
    const float* __restrict__ fc_b,
    float* __restrict__ MU, float* __restrict__ RS)
{
    __shared__ float qt[512];
    __shared__ float red[54 * 8];
    __shared__ float S[54];

    int k = blockIdx.x, b = blockIdx.y;
    long rk = (long)b * LK_ + k;
    int tid = threadIdx.x, lane = tid & 31, wid = tid >> 5;

    float2 vf[8];
#pragma unroll
    for (int h = 0; h < 8; ++h)
        vf[h] = ((const float2*)(VF + (long)h * (B_ * LK_ * DM_) + rk * DM_))[tid];
    float2 bb = ((const float2*)(A + rk * DM_))[tid];
    float2 qv = ((const float2*)(qin + rk * DM_))[tid];
    float2 fb = ((const float2*)fc_b)[tid];
    bb.x += qv.x + fb.x; bb.y += qv.y + fb.y;
    for (int e = tid; e < 512; e += 256) qt[e] = QT[rk * 512 + e];

    float part[54];
    part[0] = bb.x + bb.y;
#pragma unroll
    for (int h = 0; h < 8; ++h) part[1 + h] = vf[h].x + vf[h].y;
    part[9] = bb.x * bb.x + bb.y * bb.y;
#pragma unroll
    for (int h = 0; h < 8; ++h) part[10 + h] = bb.x * vf[h].x + bb.y * vf[h].y;
    {
        int c = 18;
#pragma unroll
        for (int h = 0; h < 8; ++h)
#pragma unroll
            for (int h2 = h; h2 < 8; ++h2)
                part[c++] = vf[h].x * vf[h2].x + vf[h].y * vf[h2].y;
    }
#pragma unroll
    for (int i = 0; i < 54; ++i) {
#pragma unroll
        for (int o = 16; o; o >>= 1)
            part[i] += __shfl_down_sync(0xffffffffu, part[i], o);
    }
    if (lane == 0) {
#pragma unroll
        for (int i = 0; i < 54; ++i) red[i * 8 + wid] = part[i];
    }
    __syncthreads();
    if (tid < 54) {
        float s = 0.f;
#pragma unroll
        for (int w = 0; w < 8; ++w) s += red[tid * 8 + w];
        S[tid] = s;
    }
    __syncthreads();
    if (tid < 64) {
        float g[8];
#pragma unroll
        for (int h = 0; h < 8; ++h) g[h] = qt[tid * 8 + h];
        float sum = S[0];
        float sq = S[9];
#pragma unroll
        for (int h = 0; h < 8; ++h) {
            sum += g[h] * S[1 + h];
            sq += 2.f * g[h] * S[10 + h];
        }
        int c = 18;
#pragma unroll
        for (int h = 0; h < 8; ++h)
#pragma unroll
            for (int h2 = h; h2 < 8; ++h2) {
                float co = (h == h2) ? g[h] * g[h] : 2.f * g[h] * g[h2];
                sq += co * S[c++];
            }
        float mu = sum * (1.f / 512.f);
        float var = sq * (1.f / 512.f) - mu * mu;
        MU[rk * 64 + tid] = mu;
        RS[rk * 64 + tid] = rsqrtf(var + 1e-5f);
    }
}

// ---------------- streaming combine epilogue (f32x2): rank-8 update + LN apply ----------------
__global__ __launch_bounds__(256) void combine_stream(
    const float* __restrict__ VF, const float* __restrict__ A,
    const float* __restrict__ QT, const float* __restrict__ qin,
    const float* __restrict__ fc_b, const float* __restrict__ ln_w,
    const float* __restrict__ ln_b, const float* __restrict__ MU,
    const float* __restrict__ RS, float* __restrict__ out)
{
    __shared__ float qt[2][512];
    __shared__ float mus[2][64], rss[2][64];

    int k0 = blockIdx.x * 2, b = blockIdx.y;
    int tid = threadIdx.x;
    int half = tid >> 7, t = tid & 127;
    long rk = (long)b * LK_ + k0 + half;
    int c4 = t * 4;

    u64t vfa[8], vfb[8];
#pragma unroll
    for (int h = 0; h < 8; ++h) {
        ulonglong2 tt = *(const ulonglong2*)(VF + (long)h * (B_ * LK_ * DM_) + rk * DM_ + c4);
        vfa[h] = tt.x; vfb[h] = tt.y;
    }
    float4 bb = *(const float4*)(A + rk * DM_ + c4);
    {
        float4 qv = *(const float4*)(qin + rk * DM_ + c4);
        float4 fb = *(const float4*)(fc_b + c4);
        bb.x += qv.x + fb.x; bb.y += qv.y + fb.y;
        bb.z += qv.z + fb.z; bb.w += qv.w + fb.w;
    }
    u64t b2a = pk2(bb.x, bb.y), b2b = pk2(bb.z, bb.w);
    float4 lw = *(const float4*)(ln_w + c4);
    float4 lb = *(const float4*)(ln_b + c4);
    u64t lw2a = pk2(lw.x, lw.y), lw2b = pk2(lw.z, lw.w);
    u64t lb2a = pk2(lb.x, lb.y), lb2b = pk2(lb.z, lb.w);

    *(float4*)&qt[half][c4] = *(const float4*)(QT + rk * 512 + c4);
    if (t < 64) {
        mus[half][t] = MU[rk * 64 + t];
        rss[half][t] = RS[rk * 64 + t];
    }
    __syncthreads();

    long obase = (long)b * (NQ_ * LK_ * DM_) + (long)(k0 + half) * DM_ + c4;
    const float* qtr = qt[half];
#pragma unroll 4
    for (int n = 0; n < NQ_; ++n) {
        u64t v0 = b2a, v1 = b2b;
#pragma unroll
        for (int h = 0; h < 8; ++h) {
            float g = qtr[n * 8 + h];
            u64t g2 = pk2(g, g);
            v0 = fma2(vfa[h], g2, v0);
            v1 = fma2(vfb[h], g2, v1);
        }
        float mu = mus[half][n], rs = rss[half][n];
        u64t nm2 = pk2(-mu, -mu), rs2 = pk2(rs, rs);
        u64t o0 = fma2(mul2(add2(v0, nm2), rs2), lw2a, lb2a);
        u64t o1 = fma2(mul2(add2(v1, nm2), rs2), lw2b, lb2b);
        ulonglong2 st;
        st.x = o0; st.y = o1;
        *(ulonglong2*)(out + obase + (long)n * (LK_ * DM_)) = st;
    }
}

// ---------------- host launcher (stream-forked DAG with serial fallback) ----------------
extern "C" void kernel_launch(void* const* d_in, const int* in_sizes, int n_in,
                              void* d_out, int out_size)
{
    (void)in_sizes; (void)n_in; (void)out_size;
    const float* q     = (const float*)d_in[0];
    const float* k     = (const float*)d_in[1];
    const float* v     = (const float*)d_in[2];
    const float* query = (const float*)d_in[3];
    const float* w_qs  = (const float*)d_in[4];
    const float* w_ks  = (const float*)d_in[5];
    const float* w_vs  = (const float*)d_in[6];
    const float* w_qu  = (const float*)d_in[7];
    const float* fc_w  = (const float*)d_in[8];
    const float* fc_b  = (const float*)d_in[9];
    const float* ln_w  = (const float*)d_in[10];
    const float* ln_b  = (const float*)d_in[11];
    float* out = (float*)d_out;

    float *pPQ, *pPK, *pPV, *pPU, *pOUT, *pA, *pQT, *pVF, *pMU, *pRS;
    cudaGetSymbolAddress((void**)&pPQ,  g_PQ);
    cudaGetSymbolAddress((void**)&pPK,  g_PK);
    cudaGetSymbolAddress((void**)&pPV,  g_PV);
    cudaGetSymbolAddress((void**)&pPU,  g_PU);
    cudaGetSymbolAddress((void**)&pOUT, g_OUT);
    cudaGetSymbolAddress((void**)&pA,   g_A);
    cudaGetSymbolAddress((void**)&pQT,  g_QT);
    cudaGetSymbolAddress((void**)&pVF,  g_VF);
    cudaGetSymbolAddress((void**)&pMU,  g_MU);
    cudaGetSymbolAddress((void**)&pRS,  g_RS);

    static bool init_done = false;
    static bool streams_ok = false;
    static cudaStream_t s1 = nullptr, s2 = nullptr;
    static cudaEvent_t evP = nullptr, ev1 = nullptr, ev2 = nullptr;
    if (!init_done) {
        init_done = true;
        cudaFuncSetAttribute(proj4,    cudaFuncAttributeMaxDynamicSharedMemorySize, GEMM_SMEM_BYTES);
        cudaFuncSetAttribute(gemm_a,   cudaFuncAttributeMaxDynamicSharedMemorySize, GEMM_SMEM_BYTES);
        cudaFuncSetAttribute(gemm_vf,  cudaFuncAttributeMaxDynamicSharedMemorySize, GEMM_SMEM_BYTES);
        cudaFuncSetAttribute(attn_self, cudaFuncAttributeMaxDynamicSharedMemorySize, 2 * 16384 * 4);
        cudaFuncSetAttribute(attn_query, cudaFuncAttributeMaxDynamicSharedMemorySize,
                             (16384 + 64 * 260 + 512) * 4);
        bool ok = true;
        ok = ok && (cudaStreamCreateWithFlags(&s1, cudaStreamNonBlocking) == cudaSuccess);
        ok = ok && (cudaStreamCreateWithFlags(&s2, cudaStreamNonBlocking) == cudaSuccess);
        ok = ok && (cudaEventCreateWithFlags(&evP, cudaEventDisableTiming) == cudaSuccess);
        ok = ok && (cudaEventCreateWithFlags(&ev1, cudaEventDisableTiming) == cudaSuccess);
        ok = ok && (cudaEventCreateWithFlags(&ev2, cudaEventDisableTiming) == cudaSuccess);
        streams_ok = ok;
    }

    dim3 thr(256);

    // Stage 1: projections (default stream)
    proj4<<<dim3(8, 8, 4), thr, GEMM_SMEM_BYTES>>>(q, k, v, query, w_qs, w_ks, w_vs, w_qu,
                                                   pPQ, pPK, pPV, pPU);

    if (streams_ok) {
        cudaEventRecord(evP, 0);
        cudaStreamWaitEvent(s1, evP, 0);
        cudaStreamWaitEvent(s2, evP, 0);

        gemm_vf<<<dim3(8, 8, 8), thr, GEMM_SMEM_BYTES, s1>>>(pPV, fc_w, pVF);
        attn_query<<<dim3(B_, H_), thr, (16384 + 64 * 260 + 512) * 4, s2>>>(pPU, pPK, pQT);

        attn_self<<<dim3(4, B_, H_), thr, 2 * 16384 * 4>>>(pPQ, pPK, pPV, pOUT);
        gemm_a<<<dim3(8, 8), thr, GEMM_SMEM_BYTES>>>(pOUT, fc_w, pA);

        cudaEventRecord(ev1, s1);
        cudaEventRecord(ev2, s2);
        cudaStreamWaitEvent(0, ev1, 0);
        cudaStreamWaitEvent(0, ev2, 0);
    } else {
        attn_self<<<dim3(4, B_, H_), thr, 2 * 16384 * 4>>>(pPQ, pPK, pPV, pOUT);
        attn_query<<<dim3(B_, H_), thr, (16384 + 64 * 260 + 512) * 4>>>(pPU, pPK, pQT);
        gemm_vf<<<dim3(8, 8, 8), thr, GEMM_SMEM_BYTES>>>(pPV, fc_w, pVF);
        gemm_a<<<dim3(8, 8), thr, GEMM_SMEM_BYTES>>>(pOUT, fc_w, pA);
    }

    // Stage 3: LN stats then streaming epilogue (default stream)
    combine_stats<<<dim3(LK_, B_), thr>>>(pVF, pA, pQT, q, fc_b, pMU, pRS);
    combine_stream<<<dim3(LK_ / 2, B_), thr>>>(pVF, pA, pQT, q, fc_b, ln_w, ln_b,
                                               pMU, pRS, out);
}